// round 9
// baseline (speedup 1.0000x reference)
#include <cuda_runtime.h>
#include <cuda_bf16.h>
#include <cstdint>

// Problem constants
#define TT   256     // sequence length
#define BB   32      // batch
#define EMB  256
#define HHD  256     // per-direction hidden
#define G4   1024    // 4*HHD
#define NT   12
#define START_IDX 10
#define STOP_IDX  11

typedef unsigned long long ull;

// ---------------- scratch (device globals; no allocation allowed) ----------
__device__ __align__(16) float g_zpre[2L * TT * G4 * BB];   // [dir][t][gate_row][b]
// h stored PAIR-PACKED: linear idx = slot*8192 + (k>>1)*64 + b*2 + (k&1)
__device__ __align__(16) float g_hs[2][(TT + 1) * HHD * BB];
__device__ __align__(16) float g_feats[BB * TT * NT];       // [b][t][tag]
__device__ int   g_bar[2 * TT];                             // per-dir per-step counters (target 256)
__device__ int   g_nbf[64];                                 // per-n-block zpre ready flags (target 16)
// bf16 split operands for the tensor-core input GEMM
__device__ __align__(16) __nv_bfloat16 g_Whi[2048 * 256];
__device__ __align__(16) __nv_bfloat16 g_Wlo[2048 * 256];
__device__ __align__(16) __nv_bfloat16 g_xhi[8192 * 256];
__device__ __align__(16) __nv_bfloat16 g_xlo[8192 * 256];

// ---------------- generic helpers ------------------------------------------
__device__ __forceinline__ void fma2(ull& d, ull a, ull b) {
    asm volatile("fma.rn.f32x2 %0, %1, %2, %0;" : "+l"(d) : "l"(a), "l"(b));
}
__device__ __forceinline__ float2 unpack2(ull v) {
    float2 f; asm("mov.b64 {%0, %1}, %2;" : "=f"(f.x), "=f"(f.y) : "l"(v)); return f;
}
__device__ __forceinline__ int ldacq(const int* p) {
    int v; asm volatile("ld.acquire.gpu.global.s32 %0, [%1];" : "=r"(v) : "l"(p)); return v;
}
__device__ __forceinline__ void redrel(int* p) {
    asm volatile("red.release.gpu.global.add.s32 [%0], 1;" :: "l"(p));
}
__device__ __forceinline__ void pause_short() {
    uint32_t x = 0;
#pragma unroll
    for (int i = 0; i < 12; i++) asm volatile("add.u32 %0, %0, 1;" : "+r"(x));
}
__device__ __forceinline__ float sigf(float x) {
    float e = __expf(-x);
    return __fdividef(1.0f, 1.0f + e);
}
__device__ __forceinline__ float tanhfast(float x) {
    float ax = fminf(fabsf(x), 15.0f);
    float e = __expf(2.0f * ax);
    float t = __fdividef(e - 1.0f, e + 1.0f);
    return copysignf(t, x);
}
__device__ __forceinline__ uint32_t smem_u32(const void* p) {
    uint32_t a;
    asm("{ .reg .u64 t; cvta.to.shared.u64 t, %1; cvt.u32.u64 %0, t; }" : "=r"(a) : "l"(p));
    return a;
}
__device__ __forceinline__ void ldsm4(uint32_t& r0, uint32_t& r1, uint32_t& r2, uint32_t& r3,
                                      uint32_t addr) {
    asm volatile("ldmatrix.sync.aligned.m8n8.x4.shared.b16 {%0,%1,%2,%3}, [%4];"
                 : "=r"(r0), "=r"(r1), "=r"(r2), "=r"(r3) : "r"(addr));
}
__device__ __forceinline__ void mma16816(float* c, const uint32_t* a, const uint32_t* b) {
    asm volatile("mma.sync.aligned.m16n8k16.row.col.f32.bf16.bf16.f32 "
                 "{%0,%1,%2,%3}, {%4,%5,%6,%7}, {%8,%9}, {%0,%1,%2,%3};"
                 : "+f"(c[0]), "+f"(c[1]), "+f"(c[2]), "+f"(c[3])
                 : "r"(a[0]), "r"(a[1]), "r"(a[2]), "r"(a[3]), "r"(b[0]), "r"(b[1]));
}

// ============================================================================
// K0a: convert W_ih (both dirs) to bf16 hi/lo.  m = dir*1024 + row
// ============================================================================
__global__ void k_convW(const float* __restrict__ Wf, const float* __restrict__ Wb)
{
    int m = blockIdx.x;
    int k = threadIdx.x;
    const float* W = (m < 1024) ? Wf : Wb;
    float v = W[(m & 1023) * 256 + k];
    __nv_bfloat16 hi = __float2bfloat16(v);
    float r = v - __bfloat162float(hi);
    g_Whi[m * 256 + k] = hi;
    g_Wlo[m * 256 + k] = __float2bfloat16(r);
}

// ============================================================================
// K0b: gather embeddings and convert to bf16 hi/lo.  n = t*32 + b
// ============================================================================
__global__ void k_convX(const int* __restrict__ sent, const float* __restrict__ embed)
{
    int n = blockIdx.x;
    int t = n >> 5, b = n & 31;
    int word = sent[b * TT + t];
    int k = threadIdx.x;
    float v = embed[(long)word * 256 + k];
    __nv_bfloat16 hi = __float2bfloat16(v);
    float r = v - __bfloat162float(hi);
    g_xhi[n * 256 + k] = hi;
    g_xlo[n * 256 + k] = __float2bfloat16(r);
}

// ============================================================================
// K1b: initialize h slots (pair-packed), zero barriers + flags
// ============================================================================
__global__ void k_inith(const float* __restrict__ h0)
{
    int dir = blockIdx.x;
    int tid = threadIdx.x;
    int slot = (dir == 0) ? 0 : TT;
    for (int s = tid; s < HHD * BB; s += 256) {
        int k = s >> 5, b = s & 31;
        int idx = slot * (HHD * BB) + (k >> 1) * 64 + b * 2 + (k & 1);
        g_hs[dir][idx] = h0[dir * (BB * HHD) + b * HHD + k];
    }
    if (blockIdx.x == 0) {
        for (int i = tid; i < 2 * TT; i += 256) g_bar[i] = 0;
        if (tid < 64) g_nbf[tid] = 0;
    }
}

// ============================================================================
// Fused kernel: bid<128 -> persistent LSTM CTAs; bid>=128 -> GEMM tiles.
//
// GEMM part: mma.sync bf16 split (Wh*xh + Wh*xl + Wl*xh), tile 128x128,
//   n-blocks ordered from both ends of t so fwd+bwd recurrence get data early;
//   releases g_nbf[nb] (target 16 m-tiles) when its z_pre columns complete.
//
// LSTM part: 64 CTAs/dir; CTA owns 4 hidden units (16 gate rows), W in SMEM.
//   Single __syncthreads per step (zred parity double buffer); per-warp
//   lane0 acquire-poll of the step counter; gate warps release per-warp
//   (counter target 256 = 64 CTA x 4 warps). z_pre prefetch gated by g_nbf.
// ============================================================================
#define ASTR 40
#define GSM_AH 0
#define GSM_AL 10240
#define GSM_BH 20480
#define GSM_BL 30720
#define FUSED_SMEM 40960
// lstm view offsets
#define LSM_W    0                      // float [16][256] = 16KB
#define LSM_ZRED 16384                  // float [2][4][16][32] = 16KB
#define LSM_C    (16384 + 16384)        // float [4][32]

__global__ void __launch_bounds__(256, 2) k_main(
    const float* __restrict__ bf, const float* __restrict__ bb,
    const float* __restrict__ Whf, const float* __restrict__ Whb,
    const float* __restrict__ c0)
{
    extern __shared__ __align__(16) char smem[];
    const int tid = threadIdx.x;
    const int bid = blockIdx.x;
    const int wid = tid >> 5, lane = tid & 31;

    if (bid >= 128) {
        // ==================== GEMM tile ====================
        __nv_bfloat16* sAh = (__nv_bfloat16*)(smem + GSM_AH);
        __nv_bfloat16* sAl = (__nv_bfloat16*)(smem + GSM_AL);
        __nv_bfloat16* sBh = (__nv_bfloat16*)(smem + GSM_BH);
        __nv_bfloat16* sBl = (__nv_bfloat16*)(smem + GSM_BL);

        const int g = bid - 128;
        const int midx = g & 15;
        const int gi = g >> 4;
        const int nb = (gi & 1) ? (63 - (gi >> 1)) : (gi >> 1);
        const int m0 = midx * 128;
        const int n0 = nb * 128;
        const int wm = (wid >> 2) * 64;
        const int wn = (wid & 3) * 32;

        float acc[4][4][4];
#pragma unroll
        for (int i = 0; i < 4; i++)
#pragma unroll
            for (int j = 0; j < 4; j++)
#pragma unroll
                for (int q = 0; q < 4; q++) acc[i][j][q] = 0.f;

        const uint32_t aAh = smem_u32(sAh), aAl = smem_u32(sAl);
        const uint32_t aBh = smem_u32(sBh), aBl = smem_u32(sBl);

        const int arow = lane & 15;
        const int akq  = (lane >> 4) * 16;
        const int brow = (lane & 7) + ((lane >> 4) << 3);
        const int bkq  = ((lane >> 3) & 1) * 16;

        for (int kc = 0; kc < 8; kc++) {
            __syncthreads();
            for (int i = tid; i < 512; i += 256) {
                int r = i >> 2, cq = (i & 3) << 3;
                long srcA = (long)(m0 + r) * 256 + kc * 32 + cq;
                *(int4*)(sAh + r * ASTR + cq) = *(const int4*)(g_Whi + srcA);
                *(int4*)(sAl + r * ASTR + cq) = *(const int4*)(g_Wlo + srcA);
                long srcB = (long)(n0 + r) * 256 + kc * 32 + cq;
                *(int4*)(sBh + r * ASTR + cq) = *(const int4*)(g_xhi + srcB);
                *(int4*)(sBl + r * ASTR + cq) = *(const int4*)(g_xlo + srcB);
            }
            __syncthreads();

#pragma unroll
            for (int ks = 0; ks < 2; ks++) {
                const int akb = ks * 32 + akq;
                const int bkb = ks * 32 + bkq;
                uint32_t Ah[4][4], Bh[4][2], Bl[4][2];
#pragma unroll
                for (int mf = 0; mf < 4; mf++) {
                    uint32_t ad = aAh + (uint32_t)((wm + mf * 16 + arow) * (ASTR * 2)) + akb;
                    ldsm4(Ah[mf][0], Ah[mf][1], Ah[mf][2], Ah[mf][3], ad);
                }
#pragma unroll
                for (int nf2 = 0; nf2 < 2; nf2++) {
                    uint32_t bo = (uint32_t)((wn + nf2 * 16 + brow) * (ASTR * 2)) + bkb;
                    uint32_t r0, r1, r2, r3;
                    ldsm4(r0, r1, r2, r3, aBh + bo);
                    Bh[nf2 * 2][0] = r0; Bh[nf2 * 2][1] = r1;
                    Bh[nf2 * 2 + 1][0] = r2; Bh[nf2 * 2 + 1][1] = r3;
                    ldsm4(r0, r1, r2, r3, aBl + bo);
                    Bl[nf2 * 2][0] = r0; Bl[nf2 * 2][1] = r1;
                    Bl[nf2 * 2 + 1][0] = r2; Bl[nf2 * 2 + 1][1] = r3;
                }
#pragma unroll
                for (int mf = 0; mf < 4; mf++)
#pragma unroll
                    for (int nf = 0; nf < 4; nf++) {
                        mma16816(acc[mf][nf], Ah[mf], Bh[nf]);
                        mma16816(acc[mf][nf], Ah[mf], Bl[nf]);
                    }
#pragma unroll
                for (int mf = 0; mf < 4; mf++) {
                    uint32_t Al[4];
                    uint32_t ad = aAl + (uint32_t)((wm + mf * 16 + arow) * (ASTR * 2)) + akb;
                    ldsm4(Al[0], Al[1], Al[2], Al[3], ad);
#pragma unroll
                    for (int nf = 0; nf < 4; nf++)
                        mma16816(acc[mf][nf], Al, Bh[nf]);
                }
            }
        }

        // epilogue
#pragma unroll
        for (int mf = 0; mf < 4; mf++) {
            int m = m0 + wm + mf * 16 + (lane >> 2);
            int dirA = m >> 10, gA = m & 1023;
            int mB = m + 8;
            int gB = mB & 1023;
            float biasA = dirA ? bb[gA] : bf[gA];
            float biasB = (mB >> 10) ? bb[gB] : bf[gB];
#pragma unroll
            for (int nf = 0; nf < 4; nf++) {
                int n = n0 + wn + nf * 8 + 2 * (lane & 3);
                int t = n >> 5, b = n & 31;
                float* zpA = g_zpre + ((long)dirA * TT + t) * (G4 * BB) + (long)gA * BB + b;
                *(float2*)zpA = make_float2(acc[mf][nf][0] + biasA, acc[mf][nf][1] + biasA);
                float* zpB = g_zpre + ((long)(mB >> 10) * TT + t) * (G4 * BB) + (long)gB * BB + b;
                *(float2*)zpB = make_float2(acc[mf][nf][2] + biasB, acc[mf][nf][3] + biasB);
            }
        }
        __syncthreads();
        if (tid == 0) redrel(&g_nbf[nb]);
        return;
    }

    // ==================== persistent LSTM CTA ====================
    float (*Wsm)[256]     = (float(*)[256])(smem + LSM_W);
    float (*zred)[4][16][32] = (float(*)[4][16][32])(smem + LSM_ZRED);
    float (*csm)[32]      = (float(*)[32])(smem + LSM_C);

    const int w = wid, l = lane;
    const int kc = w >> 1;          // 0..3 : k-chunk of 64
    const int rh = w & 1;           // 0..1 : row half (8 rows)
    const int cid = bid;
    const int dir = cid >> 6;
    const int j0 = (cid & 63) * 4;
    const int jj = w & 3;           // gate warp index (w<4)
    const int b  = l;

    const float* Wh = dir ? Whb : Whf;
#pragma unroll
    for (int i = 0; i < 4; i++) {
        int s = tid + i * 256;
        int r = s >> 6;
        int kq = (s & 63) << 2;
        int gate = r >> 2, jr = r & 3;
        float4 v = *(const float4*)(Wh + (gate * HHD + j0 + jr) * HHD + kq);
        *(float4*)&Wsm[r][kq] = v;
    }
    if (w < 4) {
        csm[jj][b] = c0[dir * (BB * HHD) + b * HHD + j0 + jj];
    }
    __syncthreads();

    float* hsBase = g_hs[dir];
    int* bar = g_bar + dir * TT;
    const long zdirbase = (long)dir * (TT * G4 * BB);
    int last_nb = -1;

    for (int s = 0; s < TT; s++) {
        const int t = (dir == 0) ? s : (TT - 1 - s);
        const int rslot = (dir == 0) ? s : (t + 1);
        const int wslot = (dir == 0) ? (s + 1) : t;
        const int par = s & 1;

        // ---- prefetch z_pre (gated on gemm flags; off critical path) ----
        float zp0, zp1, zp2, zp3;
        if (w < 4) {
            int nb = t >> 2;
            if (nb != last_nb) {
                if (lane == 0) {
                    while (ldacq(&g_nbf[nb]) < 16) pause_short();
                }
                __syncwarp();
                last_nb = nb;
            }
            const float* zb = g_zpre + zdirbase + (long)t * (G4 * BB) + (j0 + jj) * BB + b;
            zp0 = zb[0 * HHD * BB];
            zp1 = zb[1 * HHD * BB];
            zp2 = zb[2 * HHD * BB];
            zp3 = zb[3 * HHD * BB];
        }

        // ---- wait for previous step's h (per-warp lane0 poll) ----
        if (s > 0) {
            if (lane == 0) {
                while (ldacq(&bar[s - 1]) < 256) pause_short();
            }
            __syncwarp();
        }

        // ---- load this warp's 64-k chunk of h (pair-packed LDG.64) ----
        const ull* hp2 = (const ull*)(hsBase + rslot * (HHD * BB)) + kc * 32 * 32 + l;
        ull hreg2[32];
#pragma unroll
        for (int q = 0; q < 32; q++) hreg2[q] = hp2[q * 32];

        // ---- 8 rows x 64 k partial dots; W via LDS.128 ----
#pragma unroll
        for (int rr = 0; rr < 8; rr++) {
            const int r = rh * 8 + rr;
            const ulonglong2* W4 = (const ulonglong2*)&Wsm[r][kc * 64];
            ull a0 = 0ULL, a1 = 0ULL, a2 = 0ULL, a3 = 0ULL;
#pragma unroll
            for (int q4 = 0; q4 < 16; q4 += 2) {
                ulonglong2 wv0 = W4[q4];
                fma2(a0, wv0.x, hreg2[2 * q4]);
                fma2(a1, wv0.y, hreg2[2 * q4 + 1]);
                ulonglong2 wv1 = W4[q4 + 1];
                fma2(a2, wv1.x, hreg2[2 * q4 + 2]);
                fma2(a3, wv1.y, hreg2[2 * q4 + 3]);
            }
            float2 f0 = unpack2(a0), f1 = unpack2(a1);
            float2 f2 = unpack2(a2), f3 = unpack2(a3);
            zred[par][kc][r][l] = ((f0.x + f0.y) + (f1.x + f1.y))
                                + ((f2.x + f2.y) + (f3.x + f3.y));
        }
        __syncthreads();   // single block-wide sync per step

        // ---- gate warps: reduce + gates + h store + per-warp release ----
        if (w < 4) {
            float zi = zp0, zf = zp1, zg = zp2, zo = zp3;
#pragma unroll
            for (int c = 0; c < 4; c++) {
                zi += zred[par][c][0 * 4 + jj][b];
                zf += zred[par][c][1 * 4 + jj][b];
                zg += zred[par][c][2 * 4 + jj][b];
                zo += zred[par][c][3 * 4 + jj][b];
            }
            float cc = sigf(zf) * csm[jj][b] + sigf(zi) * tanhfast(zg);
            csm[jj][b] = cc;
            float h = sigf(zo) * tanhfast(cc);
            int j = j0 + jj;
            hsBase[wslot * (HHD * BB) + (j >> 1) * 64 + b * 2 + (j & 1)] = h;
            __syncwarp();
            if (lane == 0) redrel(&bar[s]);
        }
    }
}

// ============================================================================
// K3: output projection.  SMEM-staged h (64KB) + fma2. warp=tag, lane=b.
// ============================================================================
__global__ void __launch_bounds__(384) k_proj(
    const float* __restrict__ Wout, const float* __restrict__ bout)
{
    extern __shared__ float hsm[];    // [2][8192] floats = 64 KB
    const int t = blockIdx.x;
    const int tid = threadIdx.x;
    const int tag = tid >> 5;
    const int l = tid & 31;

    const float4* hf = (const float4*)(g_hs[0] + (t + 1) * (HHD * BB));
    const float4* hb = (const float4*)(g_hs[1] + t * (HHD * BB));
    float4* sf = (float4*)hsm;
    float4* sbp = (float4*)(hsm + HHD * BB);
    for (int i = tid; i < (HHD * BB) / 4; i += 384) {
        sf[i] = hf[i];
        sbp[i] = hb[i];
    }
    __syncthreads();

    const ull* w2f = (const ull*)(Wout + tag * 512);
    const ull* w2b = w2f + 128;
    const ull* hf2 = (const ull*)hsm;
    const ull* hb2 = (const ull*)(hsm + HHD * BB);

    ull a0 = 0ULL, a1 = 0ULL, a2 = 0ULL, a3 = 0ULL;
#pragma unroll
    for (int p = 0; p < 128; p += 4) {
        fma2(a0, w2f[p],     hf2[(p + 0) * 32 + l]);
        fma2(a1, w2f[p + 1], hf2[(p + 1) * 32 + l]);
        fma2(a2, w2f[p + 2], hf2[(p + 2) * 32 + l]);
        fma2(a3, w2f[p + 3], hf2[(p + 3) * 32 + l]);
    }
#pragma unroll
    for (int p = 0; p < 128; p += 4) {
        fma2(a0, w2b[p],     hb2[(p + 0) * 32 + l]);
        fma2(a1, w2b[p + 1], hb2[(p + 1) * 32 + l]);
        fma2(a2, w2b[p + 2], hb2[(p + 2) * 32 + l]);
        fma2(a3, w2b[p + 3], hb2[(p + 3) * 32 + l]);
    }
    float2 f0 = unpack2(a0), f1 = unpack2(a1);
    float2 f2 = unpack2(a2), f3 = unpack2(a3);
    float acc = ((f0.x + f0.y) + (f1.x + f1.y))
              + ((f2.x + f2.y) + (f3.x + f3.y)) + bout[tag];
    g_feats[(l * TT + t) * NT + tag] = acc;
}

// ============================================================================
// K4: Viterbi decode (one warp per batch element) + backtrace.
// ============================================================================
__global__ void __launch_bounds__(32) k_viterbi(
    const float* __restrict__ trans, float* __restrict__ out)
{
    __shared__ float tsm[NT * NT];
    __shared__ float fv[NT];
    __shared__ signed char bp[TT][NT];
    __shared__ float fsm[TT * NT];

    const int b = blockIdx.x;
    const int tid = threadIdx.x;

    const float* fb = g_feats + (long)b * TT * NT;
    for (int i = tid; i < TT * NT; i += 32) fsm[i] = fb[i];
    for (int i = tid; i < NT * NT; i += 32) tsm[i] = trans[i];
    if (tid < NT) fv[tid] = (tid == START_IDX) ? 0.0f : -10000.0f;
    __syncwarp();

    for (int t = 0; t < TT; t++) {
        float bestv = -1e30f; int bestp = 0;
        if (tid < NT) {
            bestv = fv[0] + tsm[tid * NT + 0]; bestp = 0;
#pragma unroll
            for (int p = 1; p < NT; p++) {
                float v = fv[p] + tsm[tid * NT + p];
                if (v > bestv) { bestv = v; bestp = p; }
            }
        }
        __syncwarp();
        if (tid < NT) {
            fv[tid] = bestv + fsm[t * NT + tid];
            bp[t][tid] = (signed char)bestp;
        }
        __syncwarp();
    }

    if (tid == 0) {
        float best = fv[0] + tsm[STOP_IDX * NT + 0]; int bt = 0;
#pragma unroll
        for (int n = 1; n < NT; n++) {
            float v = fv[n] + tsm[STOP_IDX * NT + n];
            if (v > best) { best = v; bt = n; }
        }
        out[b] = best;
        int tag = bt;
        for (int t = TT - 1; t >= 0; t--) {
            out[32 + b * TT + t] = (float)tag;
            tag = bp[t][tag];
        }
    }
}

// ============================================================================
extern "C" void kernel_launch(void* const* d_in, const int* in_sizes, int n_in,
                              void* d_out, int out_size)
{
    const int*   sent  = (const int*)  d_in[0];
    const float* embed = (const float*)d_in[1];
    const float* Wihf  = (const float*)d_in[2];
    const float* Whhf  = (const float*)d_in[3];
    const float* bf    = (const float*)d_in[4];
    const float* Wihb  = (const float*)d_in[5];
    const float* Whhb  = (const float*)d_in[6];
    const float* bb    = (const float*)d_in[7];
    const float* Wout  = (const float*)d_in[8];
    const float* bout  = (const float*)d_in[9];
    const float* trans = (const float*)d_in[10];
    const float* h0    = (const float*)d_in[11];
    const float* c0    = (const float*)d_in[12];
    float* out = (float*)d_out;

    cudaFuncSetAttribute(k_proj, cudaFuncAttributeMaxDynamicSharedMemorySize, 65536);

    k_convW<<<2048, 256>>>(Wihf, Wihb);
    k_convX<<<8192, 256>>>(sent, embed);
    k_inith<<<2, 256>>>(h0);
    k_main<<<128 + 1024, 256, FUSED_SMEM>>>(bf, bb, Whhf, Whhb, c0);
    k_proj<<<TT, 384, 65536>>>(Wout, bout);
    k_viterbi<<<BB, 32>>>(trans, out);
}

// round 10
// speedup vs baseline: 1.2910x; 1.2910x over previous
#include <cuda_runtime.h>
#include <cuda_bf16.h>
#include <cstdint>

// Problem constants
#define TT   256     // sequence length
#define BB   32      // batch
#define EMB  256
#define HHD  256     // per-direction hidden
#define G4   1024    // 4*HHD
#define NT   12
#define START_IDX 10
#define STOP_IDX  11
#define BARSTR 32    // barrier slot stride in ints (128B line padding)

typedef unsigned long long ull;

// ---------------- scratch (device globals; no allocation allowed) ----------
__device__ __align__(16) float g_zpre[2L * TT * G4 * BB];   // [dir][t][gate_row][b]
// h stored PAIR-PACKED: linear idx = slot*8192 + (k>>1)*64 + b*2 + (k&1)
__device__ __align__(16) float g_hs[2][(TT + 1) * HHD * BB];
__device__ __align__(16) float g_feats[BB * TT * NT];       // [b][t][tag]
__device__ int   g_bar[2 * TT * BARSTR];                    // padded step counters (target 256)
// bf16 split operands for the tensor-core input GEMM
__device__ __align__(16) __nv_bfloat16 g_Whi[2048 * 256];
__device__ __align__(16) __nv_bfloat16 g_Wlo[2048 * 256];
__device__ __align__(16) __nv_bfloat16 g_xhi[8192 * 256];
__device__ __align__(16) __nv_bfloat16 g_xlo[8192 * 256];

// ---------------- generic helpers ------------------------------------------
__device__ __forceinline__ void fma2(ull& d, ull a, ull b) {
    asm volatile("fma.rn.f32x2 %0, %1, %2, %0;" : "+l"(d) : "l"(a), "l"(b));
}
__device__ __forceinline__ float2 unpack2(ull v) {
    float2 f; asm("mov.b64 {%0, %1}, %2;" : "=f"(f.x), "=f"(f.y) : "l"(v)); return f;
}
__device__ __forceinline__ int ldacq(const int* p) {
    int v; asm volatile("ld.acquire.gpu.global.s32 %0, [%1];" : "=r"(v) : "l"(p)); return v;
}
__device__ __forceinline__ void redrel(int* p) {
    asm volatile("red.release.gpu.global.add.s32 [%0], 1;" :: "l"(p));
}
__device__ __forceinline__ void pause_short() {
    uint32_t x = 0;
#pragma unroll
    for (int i = 0; i < 12; i++) asm volatile("add.u32 %0, %0, 1;" : "+r"(x));
}
__device__ __forceinline__ float sigf(float x) {
    float e = __expf(-x);
    return __fdividef(1.0f, 1.0f + e);
}
__device__ __forceinline__ float tanhfast(float x) {
    float ax = fminf(fabsf(x), 15.0f);
    float e = __expf(2.0f * ax);
    float t = __fdividef(e - 1.0f, e + 1.0f);
    return copysignf(t, x);
}
__device__ __forceinline__ uint32_t smem_u32(const void* p) {
    uint32_t a;
    asm("{ .reg .u64 t; cvta.to.shared.u64 t, %1; cvt.u32.u64 %0, t; }" : "=r"(a) : "l"(p));
    return a;
}
__device__ __forceinline__ void ldsm4(uint32_t& r0, uint32_t& r1, uint32_t& r2, uint32_t& r3,
                                      uint32_t addr) {
    asm volatile("ldmatrix.sync.aligned.m8n8.x4.shared.b16 {%0,%1,%2,%3}, [%4];"
                 : "=r"(r0), "=r"(r1), "=r"(r2), "=r"(r3) : "r"(addr));
}
__device__ __forceinline__ void mma16816(float* c, const uint32_t* a, const uint32_t* b) {
    asm volatile("mma.sync.aligned.m16n8k16.row.col.f32.bf16.bf16.f32 "
                 "{%0,%1,%2,%3}, {%4,%5,%6,%7}, {%8,%9}, {%0,%1,%2,%3};"
                 : "+f"(c[0]), "+f"(c[1]), "+f"(c[2]), "+f"(c[3])
                 : "r"(a[0]), "r"(a[1]), "r"(a[2]), "r"(a[3]), "r"(b[0]), "r"(b[1]));
}

// ============================================================================
// K0a: convert W_ih (both dirs) to bf16 hi/lo.  m = dir*1024 + row
// ============================================================================
__global__ void k_convW(const float* __restrict__ Wf, const float* __restrict__ Wb)
{
    int m = blockIdx.x;
    int k = threadIdx.x;
    const float* W = (m < 1024) ? Wf : Wb;
    float v = W[(m & 1023) * 256 + k];
    __nv_bfloat16 hi = __float2bfloat16(v);
    float r = v - __bfloat162float(hi);
    g_Whi[m * 256 + k] = hi;
    g_Wlo[m * 256 + k] = __float2bfloat16(r);
}

// ============================================================================
// K0b: gather embeddings and convert to bf16 hi/lo.  n = t*32 + b
// ============================================================================
__global__ void k_convX(const int* __restrict__ sent, const float* __restrict__ embed)
{
    int n = blockIdx.x;
    int t = n >> 5, b = n & 31;
    int word = sent[b * TT + t];
    int k = threadIdx.x;
    float v = embed[(long)word * 256 + k];
    __nv_bfloat16 hi = __float2bfloat16(v);
    float r = v - __bfloat162float(hi);
    g_xhi[n * 256 + k] = hi;
    g_xlo[n * 256 + k] = __float2bfloat16(r);
}

// ============================================================================
// K1: tensor-core input GEMM via mma.sync bf16 split (R7 design, unchanged).
// ============================================================================
#define ASTR 40
__global__ void __launch_bounds__(256, 2) k_ingemm_mma(
    const float* __restrict__ bf, const float* __restrict__ bb)
{
    __shared__ __align__(16) __nv_bfloat16 sAh[128 * ASTR];
    __shared__ __align__(16) __nv_bfloat16 sAl[128 * ASTR];
    __shared__ __align__(16) __nv_bfloat16 sBh[128 * ASTR];
    __shared__ __align__(16) __nv_bfloat16 sBl[128 * ASTR];

    const int tid = threadIdx.x;
    const int wid = tid >> 5, lane = tid & 31;
    const int m0 = blockIdx.y * 128;
    const int n0 = blockIdx.x * 128;
    const int wm = (wid >> 2) * 64;
    const int wn = (wid & 3) * 32;

    float acc[4][4][4];
#pragma unroll
    for (int i = 0; i < 4; i++)
#pragma unroll
        for (int j = 0; j < 4; j++)
#pragma unroll
            for (int q = 0; q < 4; q++) acc[i][j][q] = 0.f;

    const uint32_t aAh = smem_u32(sAh), aAl = smem_u32(sAl);
    const uint32_t aBh = smem_u32(sBh), aBl = smem_u32(sBl);

    const int arow = lane & 15;
    const int akq  = (lane >> 4) * 16;
    const int brow = (lane & 7) + ((lane >> 4) << 3);
    const int bkq  = ((lane >> 3) & 1) * 16;

    for (int kc = 0; kc < 8; kc++) {
        __syncthreads();
        for (int i = tid; i < 512; i += 256) {
            int r = i >> 2, cq = (i & 3) << 3;
            long srcA = (long)(m0 + r) * 256 + kc * 32 + cq;
            *(int4*)(sAh + r * ASTR + cq) = *(const int4*)(g_Whi + srcA);
            *(int4*)(sAl + r * ASTR + cq) = *(const int4*)(g_Wlo + srcA);
            long srcB = (long)(n0 + r) * 256 + kc * 32 + cq;
            *(int4*)(sBh + r * ASTR + cq) = *(const int4*)(g_xhi + srcB);
            *(int4*)(sBl + r * ASTR + cq) = *(const int4*)(g_xlo + srcB);
        }
        __syncthreads();

#pragma unroll
        for (int ks = 0; ks < 2; ks++) {
            const int akb = ks * 32 + akq;
            const int bkb = ks * 32 + bkq;
            uint32_t Ah[4][4], Bh[4][2], Bl[4][2];
#pragma unroll
            for (int mf = 0; mf < 4; mf++) {
                uint32_t ad = aAh + (uint32_t)((wm + mf * 16 + arow) * (ASTR * 2)) + akb;
                ldsm4(Ah[mf][0], Ah[mf][1], Ah[mf][2], Ah[mf][3], ad);
            }
#pragma unroll
            for (int nf2 = 0; nf2 < 2; nf2++) {
                uint32_t bo = (uint32_t)((wn + nf2 * 16 + brow) * (ASTR * 2)) + bkb;
                uint32_t r0, r1, r2, r3;
                ldsm4(r0, r1, r2, r3, aBh + bo);
                Bh[nf2 * 2][0] = r0; Bh[nf2 * 2][1] = r1;
                Bh[nf2 * 2 + 1][0] = r2; Bh[nf2 * 2 + 1][1] = r3;
                ldsm4(r0, r1, r2, r3, aBl + bo);
                Bl[nf2 * 2][0] = r0; Bl[nf2 * 2][1] = r1;
                Bl[nf2 * 2 + 1][0] = r2; Bl[nf2 * 2 + 1][1] = r3;
            }
#pragma unroll
            for (int mf = 0; mf < 4; mf++)
#pragma unroll
                for (int nf = 0; nf < 4; nf++) {
                    mma16816(acc[mf][nf], Ah[mf], Bh[nf]);
                    mma16816(acc[mf][nf], Ah[mf], Bl[nf]);
                }
#pragma unroll
            for (int mf = 0; mf < 4; mf++) {
                uint32_t Al[4];
                uint32_t ad = aAl + (uint32_t)((wm + mf * 16 + arow) * (ASTR * 2)) + akb;
                ldsm4(Al[0], Al[1], Al[2], Al[3], ad);
#pragma unroll
                for (int nf = 0; nf < 4; nf++)
                    mma16816(acc[mf][nf], Al, Bh[nf]);
            }
        }
    }

#pragma unroll
    for (int mf = 0; mf < 4; mf++) {
        int m = m0 + wm + mf * 16 + (lane >> 2);
        int dirA = m >> 10, gA = m & 1023;
        int mB = m + 8;
        int gB = mB & 1023;
        float biasA = dirA ? bb[gA] : bf[gA];
        float biasB = (mB >> 10) ? bb[gB] : bf[gB];
#pragma unroll
        for (int nf = 0; nf < 4; nf++) {
            int n = n0 + wn + nf * 8 + 2 * (lane & 3);
            int t = n >> 5, b = n & 31;
            float* zpA = g_zpre + ((long)dirA * TT + t) * (G4 * BB) + (long)gA * BB + b;
            *(float2*)zpA = make_float2(acc[mf][nf][0] + biasA, acc[mf][nf][1] + biasA);
            float* zpB = g_zpre + ((long)(mB >> 10) * TT + t) * (G4 * BB) + (long)gB * BB + b;
            *(float2*)zpB = make_float2(acc[mf][nf][2] + biasB, acc[mf][nf][3] + biasB);
        }
    }
}

// ============================================================================
// K1b: initialize h slots (pair-packed) and zero padded barriers
// ============================================================================
__global__ void k_inith(const float* __restrict__ h0)
{
    int dir = blockIdx.x;
    int tid = threadIdx.x;
    int slot = (dir == 0) ? 0 : TT;
    for (int s = tid; s < HHD * BB; s += 256) {
        int k = s >> 5, b = s & 31;
        int idx = slot * (HHD * BB) + (k >> 1) * 64 + b * 2 + (k & 1);
        g_hs[dir][idx] = h0[dir * (BB * HHD) + b * HHD + k];
    }
    if (blockIdx.x == 0) {
        for (int i = tid; i < 2 * TT * BARSTR; i += 256) g_bar[i] = 0;
    }
}

// ============================================================================
// K2: persistent bi-directional LSTM recurrence, warp-specialized.
// 128 CTAs x 384 threads: dir = bid>>6, j-group = bid&63 (4 hidden units).
// Warps 0-7: compute (kc = w>>1: 64-k chunk, rh = w&1: 8 gate rows).
//   tid0 polls padded global step counter; named bar 1 (256) wakes compute;
//   zred[parity] write; bar.arrive 2 hands off to gate warps.
// Warps 8-11: gates. Prefetch z_pre, bar.sync 2 (384), reduce+gates+h STG,
//   per-warp release (counter target 256 = 64 CTA x 4 warps).
// ============================================================================
__global__ void __launch_bounds__(384, 1) k_lstm(
    const float* __restrict__ Whf, const float* __restrict__ Whb,
    const float* __restrict__ c0)
{
    __shared__ __align__(16) float Wsm[16][256];   // 16 KB
    __shared__ float zred[2][4][16][32];           // 16 KB (parity buffered)
    __shared__ float csm[4][32];

    const int tid = threadIdx.x;
    const int w = tid >> 5, lane = tid & 31;
    const int dir = blockIdx.x >> 6;
    const int j0 = (blockIdx.x & 63) * 4;
    const int b  = lane;

    const float* Wh = dir ? Whb : Whf;
    for (int i = tid; i < 1024; i += 384) {       // 1024 float4 slots
        int r = i >> 6;
        int kq = (i & 63) << 2;
        int gate = r >> 2, jr = r & 3;
        float4 v = *(const float4*)(Wh + (gate * HHD + j0 + jr) * HHD + kq);
        *(float4*)&Wsm[r][kq] = v;
    }
    if (w >= 8) {
        int jj = w - 8;
        csm[jj][b] = c0[dir * (BB * HHD) + b * HHD + j0 + jj];
    }
    __syncthreads();

    float* hsBase = g_hs[dir];
    int* bar = g_bar + dir * TT * BARSTR;
    const long zdirbase = (long)dir * (TT * G4 * BB);

    if (w < 8) {
        // ==================== compute warps ====================
        const int kc = w >> 1, rh = w & 1;
        for (int s = 0; s < TT; s++) {
            const int t = (dir == 0) ? s : (TT - 1 - s);
            const int rslot = (dir == 0) ? s : (t + 1);
            const int par = s & 1;

            if (s > 0) {
                if (tid == 0) {
                    while (ldacq(&bar[(s - 1) * BARSTR]) < 256) pause_short();
                }
            }
            asm volatile("bar.sync 1, 256;" ::: "memory");

            const ull* hp2 = (const ull*)(hsBase + rslot * (HHD * BB)) + kc * 32 * 32 + lane;
            ull hreg2[32];
#pragma unroll
            for (int q = 0; q < 32; q++) hreg2[q] = hp2[q * 32];

#pragma unroll
            for (int rr = 0; rr < 8; rr++) {
                const int r = rh * 8 + rr;
                const ulonglong2* W4 = (const ulonglong2*)&Wsm[r][kc * 64];
                ull a0 = 0ULL, a1 = 0ULL, a2 = 0ULL, a3 = 0ULL;
#pragma unroll
                for (int q4 = 0; q4 < 16; q4 += 2) {
                    ulonglong2 wv0 = W4[q4];
                    fma2(a0, wv0.x, hreg2[2 * q4]);
                    fma2(a1, wv0.y, hreg2[2 * q4 + 1]);
                    ulonglong2 wv1 = W4[q4 + 1];
                    fma2(a2, wv1.x, hreg2[2 * q4 + 2]);
                    fma2(a3, wv1.y, hreg2[2 * q4 + 3]);
                }
                float2 f0 = unpack2(a0), f1 = unpack2(a1);
                float2 f2 = unpack2(a2), f3 = unpack2(a3);
                zred[par][kc][r][lane] = ((f0.x + f0.y) + (f1.x + f1.y))
                                       + ((f2.x + f2.y) + (f3.x + f3.y));
            }
            asm volatile("bar.arrive 2, 384;" ::: "memory");
        }
    } else {
        // ==================== gate warps ====================
        const int jj = w - 8;
        for (int s = 0; s < TT; s++) {
            const int t = (dir == 0) ? s : (TT - 1 - s);
            const int wslot = (dir == 0) ? (s + 1) : t;
            const int par = s & 1;

            // prefetch z_pre for this step (off the compute critical path)
            const float* zb = g_zpre + zdirbase + (long)t * (G4 * BB) + (j0 + jj) * BB + b;
            float zp0 = zb[0 * HHD * BB];
            float zp1 = zb[1 * HHD * BB];
            float zp2 = zb[2 * HHD * BB];
            float zp3 = zb[3 * HHD * BB];

            asm volatile("bar.sync 2, 384;" ::: "memory");

            float zi = zp0, zf = zp1, zg = zp2, zo = zp3;
#pragma unroll
            for (int c = 0; c < 4; c++) {
                zi += zred[par][c][0 * 4 + jj][b];
                zf += zred[par][c][1 * 4 + jj][b];
                zg += zred[par][c][2 * 4 + jj][b];
                zo += zred[par][c][3 * 4 + jj][b];
            }
            float cc = sigf(zf) * csm[jj][b] + sigf(zi) * tanhfast(zg);
            csm[jj][b] = cc;
            float h = sigf(zo) * tanhfast(cc);
            int j = j0 + jj;
            hsBase[wslot * (HHD * BB) + (j >> 1) * 64 + b * 2 + (j & 1)] = h;
            __syncwarp();
            if (lane == 0) redrel(&bar[s * BARSTR]);
        }
    }
}

// ============================================================================
// K3: output projection.  SMEM-staged h (64KB) + fma2. warp=tag, lane=b.
// ============================================================================
__global__ void __launch_bounds__(384) k_proj(
    const float* __restrict__ Wout, const float* __restrict__ bout)
{
    extern __shared__ float hsm[];    // [2][8192] floats = 64 KB
    const int t = blockIdx.x;
    const int tid = threadIdx.x;
    const int tag = tid >> 5;
    const int l = tid & 31;

    const float4* hf = (const float4*)(g_hs[0] + (t + 1) * (HHD * BB));
    const float4* hb = (const float4*)(g_hs[1] + t * (HHD * BB));
    float4* sf = (float4*)hsm;
    float4* sbp = (float4*)(hsm + HHD * BB);
    for (int i = tid; i < (HHD * BB) / 4; i += 384) {
        sf[i] = hf[i];
        sbp[i] = hb[i];
    }
    __syncthreads();

    const ull* w2f = (const ull*)(Wout + tag * 512);
    const ull* w2b = w2f + 128;
    const ull* hf2 = (const ull*)hsm;
    const ull* hb2 = (const ull*)(hsm + HHD * BB);

    ull a0 = 0ULL, a1 = 0ULL, a2 = 0ULL, a3 = 0ULL;
#pragma unroll
    for (int p = 0; p < 128; p += 4) {
        fma2(a0, w2f[p],     hf2[(p + 0) * 32 + l]);
        fma2(a1, w2f[p + 1], hf2[(p + 1) * 32 + l]);
        fma2(a2, w2f[p + 2], hf2[(p + 2) * 32 + l]);
        fma2(a3, w2f[p + 3], hf2[(p + 3) * 32 + l]);
    }
#pragma unroll
    for (int p = 0; p < 128; p += 4) {
        fma2(a0, w2b[p],     hb2[(p + 0) * 32 + l]);
        fma2(a1, w2b[p + 1], hb2[(p + 1) * 32 + l]);
        fma2(a2, w2b[p + 2], hb2[(p + 2) * 32 + l]);
        fma2(a3, w2b[p + 3], hb2[(p + 3) * 32 + l]);
    }
    float2 f0 = unpack2(a0), f1 = unpack2(a1);
    float2 f2 = unpack2(a2), f3 = unpack2(a3);
    float acc = ((f0.x + f0.y) + (f1.x + f1.y))
              + ((f2.x + f2.y) + (f3.x + f3.y)) + bout[tag];
    g_feats[(l * TT + t) * NT + tag] = acc;
}

// ============================================================================
// K4: Viterbi decode (one warp per batch element) + backtrace.
// ============================================================================
__global__ void __launch_bounds__(32) k_viterbi(
    const float* __restrict__ trans, float* __restrict__ out)
{
    __shared__ float tsm[NT * NT];
    __shared__ float fv[NT];
    __shared__ signed char bp[TT][NT];
    __shared__ float fsm[TT * NT];

    const int b = blockIdx.x;
    const int tid = threadIdx.x;

    const float* fb = g_feats + (long)b * TT * NT;
    for (int i = tid; i < TT * NT; i += 32) fsm[i] = fb[i];
    for (int i = tid; i < NT * NT; i += 32) tsm[i] = trans[i];
    if (tid < NT) fv[tid] = (tid == START_IDX) ? 0.0f : -10000.0f;
    __syncwarp();

    for (int t = 0; t < TT; t++) {
        float bestv = -1e30f; int bestp = 0;
        if (tid < NT) {
            bestv = fv[0] + tsm[tid * NT + 0]; bestp = 0;
#pragma unroll
            for (int p = 1; p < NT; p++) {
                float v = fv[p] + tsm[tid * NT + p];
                if (v > bestv) { bestv = v; bestp = p; }
            }
        }
        __syncwarp();
        if (tid < NT) {
            fv[tid] = bestv + fsm[t * NT + tid];
            bp[t][tid] = (signed char)bestp;
        }
        __syncwarp();
    }

    if (tid == 0) {
        float best = fv[0] + tsm[STOP_IDX * NT + 0]; int bt = 0;
#pragma unroll
        for (int n = 1; n < NT; n++) {
            float v = fv[n] + tsm[STOP_IDX * NT + n];
            if (v > best) { best = v; bt = n; }
        }
        out[b] = best;
        int tag = bt;
        for (int t = TT - 1; t >= 0; t--) {
            out[32 + b * TT + t] = (float)tag;
            tag = bp[t][tag];
        }
    }
}

// ============================================================================
extern "C" void kernel_launch(void* const* d_in, const int* in_sizes, int n_in,
                              void* d_out, int out_size)
{
    const int*   sent  = (const int*)  d_in[0];
    const float* embed = (const float*)d_in[1];
    const float* Wihf  = (const float*)d_in[2];
    const float* Whhf  = (const float*)d_in[3];
    const float* bf    = (const float*)d_in[4];
    const float* Wihb  = (const float*)d_in[5];
    const float* Whhb  = (const float*)d_in[6];
    const float* bb    = (const float*)d_in[7];
    const float* Wout  = (const float*)d_in[8];
    const float* bout  = (const float*)d_in[9];
    const float* trans = (const float*)d_in[10];
    const float* h0    = (const float*)d_in[11];
    const float* c0    = (const float*)d_in[12];
    float* out = (float*)d_out;

    cudaFuncSetAttribute(k_proj, cudaFuncAttributeMaxDynamicSharedMemorySize, 65536);

    k_convW<<<2048, 256>>>(Wihf, Wihb);
    k_convX<<<8192, 256>>>(sent, embed);
    k_inith<<<2, 256>>>(h0);
    k_ingemm_mma<<<dim3(64, 16), 256>>>(bf, bb);
    k_lstm<<<128, 384>>>(Whhf, Whhb, c0);
    k_proj<<<TT, 384, 65536>>>(Wout, bout);
    k_viterbi<<<BB, 32>>>(trans, out);
}

// round 11
// speedup vs baseline: 1.4830x; 1.1487x over previous
#include <cuda_runtime.h>
#include <cuda_bf16.h>
#include <cstdint>

// Problem constants
#define TT   256     // sequence length
#define BB   32      // batch
#define EMB  256
#define HHD  256     // per-direction hidden
#define G4   1024    // 4*HHD
#define NT   12
#define START_IDX 10
#define STOP_IDX  11
#define BARSTR 32    // barrier slot stride in ints (128B line padding)

typedef unsigned long long ull;

// ---------------- scratch (device globals; no allocation allowed) ----------
__device__ __align__(16) float g_zpre[2L * TT * G4 * BB];   // [dir][t][gate_row][b]
// fp32 h (for k_proj): pair-packed idx = slot*8192 + (k>>1)*64 + b*2 + (k&1)
__device__ __align__(16) float g_hs[2][(TT + 1) * HHD * BB];
// bf16 split h (for recurrence MMA): uint32 word wi = slot*8192 + (k>>1)*64 + b*2
//   word wi   = {bf16 hi(h[2q]) , bf16 hi(h[2q+1])}   (low half = even k)
//   word wi+1 = {bf16 lo(h[2q]) , bf16 lo(h[2q+1])}
__device__ __align__(16) uint32_t g_hsbf[2][(TT + 1) * 8192];
__device__ __align__(16) float g_feats[BB * TT * NT];       // [b][t][tag]
__device__ int   g_bar[2 * TT * BARSTR];                    // padded step counters (target 256)
// bf16 split operands for input GEMM (W_ih, x) and recurrence (W_hh)
__device__ __align__(16) __nv_bfloat16 g_Whi[2048 * 256];
__device__ __align__(16) __nv_bfloat16 g_Wlo[2048 * 256];
__device__ __align__(16) __nv_bfloat16 g_Hhi[2048 * 256];   // W_hh rows m = dir*1024 + row
__device__ __align__(16) __nv_bfloat16 g_Hlo[2048 * 256];
__device__ __align__(16) __nv_bfloat16 g_xhi[8192 * 256];
__device__ __align__(16) __nv_bfloat16 g_xlo[8192 * 256];

// ---------------- generic helpers ------------------------------------------
__device__ __forceinline__ void fma2(ull& d, ull a, ull b) {
    asm volatile("fma.rn.f32x2 %0, %1, %2, %0;" : "+l"(d) : "l"(a), "l"(b));
}
__device__ __forceinline__ float2 unpack2(ull v) {
    float2 f; asm("mov.b64 {%0, %1}, %2;" : "=f"(f.x), "=f"(f.y) : "l"(v)); return f;
}
__device__ __forceinline__ int ldacq(const int* p) {
    int v; asm volatile("ld.acquire.gpu.global.s32 %0, [%1];" : "=r"(v) : "l"(p)); return v;
}
__device__ __forceinline__ void redrel(int* p) {
    asm volatile("red.release.gpu.global.add.s32 [%0], 1;" :: "l"(p));
}
__device__ __forceinline__ void pause_short() {
    uint32_t x = 0;
#pragma unroll
    for (int i = 0; i < 12; i++) asm volatile("add.u32 %0, %0, 1;" : "+r"(x));
}
__device__ __forceinline__ float sigf(float x) {
    float e = __expf(-x);
    return __fdividef(1.0f, 1.0f + e);
}
__device__ __forceinline__ float tanhfast(float x) {
    float ax = fminf(fabsf(x), 15.0f);
    float e = __expf(2.0f * ax);
    float t = __fdividef(e - 1.0f, e + 1.0f);
    return copysignf(t, x);
}
__device__ __forceinline__ uint32_t smem_u32(const void* p) {
    uint32_t a;
    asm("{ .reg .u64 t; cvta.to.shared.u64 t, %1; cvt.u32.u64 %0, t; }" : "=r"(a) : "l"(p));
    return a;
}
__device__ __forceinline__ void ldsm4(uint32_t& r0, uint32_t& r1, uint32_t& r2, uint32_t& r3,
                                      uint32_t addr) {
    asm volatile("ldmatrix.sync.aligned.m8n8.x4.shared.b16 {%0,%1,%2,%3}, [%4];"
                 : "=r"(r0), "=r"(r1), "=r"(r2), "=r"(r3) : "r"(addr));
}
__device__ __forceinline__ void mma16816(float* c, const uint32_t* a, const uint32_t* b) {
    asm volatile("mma.sync.aligned.m16n8k16.row.col.f32.bf16.bf16.f32 "
                 "{%0,%1,%2,%3}, {%4,%5,%6,%7}, {%8,%9}, {%0,%1,%2,%3};"
                 : "+f"(c[0]), "+f"(c[1]), "+f"(c[2]), "+f"(c[3])
                 : "r"(a[0]), "r"(a[1]), "r"(a[2]), "r"(a[3]), "r"(b[0]), "r"(b[1]));
}

// ============================================================================
// K0a: convert W_ih (both dirs) to bf16 hi/lo.
// ============================================================================
__global__ void k_convW(const float* __restrict__ Wf, const float* __restrict__ Wb)
{
    int m = blockIdx.x;
    int k = threadIdx.x;
    const float* W = (m < 1024) ? Wf : Wb;
    float v = W[(m & 1023) * 256 + k];
    __nv_bfloat16 hi = __float2bfloat16(v);
    float r = v - __bfloat162float(hi);
    g_Whi[m * 256 + k] = hi;
    g_Wlo[m * 256 + k] = __float2bfloat16(r);
}

// ============================================================================
// K0a2: convert W_hh (both dirs) to bf16 hi/lo.
// ============================================================================
__global__ void k_convWh(const float* __restrict__ Wf, const float* __restrict__ Wb)
{
    int m = blockIdx.x;
    int k = threadIdx.x;
    const float* W = (m < 1024) ? Wf : Wb;
    float v = W[(m & 1023) * 256 + k];
    __nv_bfloat16 hi = __float2bfloat16(v);
    float r = v - __bfloat162float(hi);
    g_Hhi[m * 256 + k] = hi;
    g_Hlo[m * 256 + k] = __float2bfloat16(r);
}

// ============================================================================
// K0b: gather embeddings and convert to bf16 hi/lo.  n = t*32 + b
// ============================================================================
__global__ void k_convX(const int* __restrict__ sent, const float* __restrict__ embed)
{
    int n = blockIdx.x;
    int t = n >> 5, b = n & 31;
    int word = sent[b * TT + t];
    int k = threadIdx.x;
    float v = embed[(long)word * 256 + k];
    __nv_bfloat16 hi = __float2bfloat16(v);
    float r = v - __bfloat162float(hi);
    g_xhi[n * 256 + k] = hi;
    g_xlo[n * 256 + k] = __float2bfloat16(r);
}

// ============================================================================
// K1: tensor-core input GEMM via mma.sync bf16 split (R7 design, unchanged).
// ============================================================================
#define ASTR 40
__global__ void __launch_bounds__(256, 2) k_ingemm_mma(
    const float* __restrict__ bf, const float* __restrict__ bb)
{
    __shared__ __align__(16) __nv_bfloat16 sAh[128 * ASTR];
    __shared__ __align__(16) __nv_bfloat16 sAl[128 * ASTR];
    __shared__ __align__(16) __nv_bfloat16 sBh[128 * ASTR];
    __shared__ __align__(16) __nv_bfloat16 sBl[128 * ASTR];

    const int tid = threadIdx.x;
    const int wid = tid >> 5, lane = tid & 31;
    const int m0 = blockIdx.y * 128;
    const int n0 = blockIdx.x * 128;
    const int wm = (wid >> 2) * 64;
    const int wn = (wid & 3) * 32;

    float acc[4][4][4];
#pragma unroll
    for (int i = 0; i < 4; i++)
#pragma unroll
        for (int j = 0; j < 4; j++)
#pragma unroll
            for (int q = 0; q < 4; q++) acc[i][j][q] = 0.f;

    const uint32_t aAh = smem_u32(sAh), aAl = smem_u32(sAl);
    const uint32_t aBh = smem_u32(sBh), aBl = smem_u32(sBl);

    const int arow = lane & 15;
    const int akq  = (lane >> 4) * 16;
    const int brow = (lane & 7) + ((lane >> 4) << 3);
    const int bkq  = ((lane >> 3) & 1) * 16;

    for (int kc = 0; kc < 8; kc++) {
        __syncthreads();
        for (int i = tid; i < 512; i += 256) {
            int r = i >> 2, cq = (i & 3) << 3;
            long srcA = (long)(m0 + r) * 256 + kc * 32 + cq;
            *(int4*)(sAh + r * ASTR + cq) = *(const int4*)(g_Whi + srcA);
            *(int4*)(sAl + r * ASTR + cq) = *(const int4*)(g_Wlo + srcA);
            long srcB = (long)(n0 + r) * 256 + kc * 32 + cq;
            *(int4*)(sBh + r * ASTR + cq) = *(const int4*)(g_xhi + srcB);
            *(int4*)(sBl + r * ASTR + cq) = *(const int4*)(g_xlo + srcB);
        }
        __syncthreads();

#pragma unroll
        for (int ks = 0; ks < 2; ks++) {
            const int akb = ks * 32 + akq;
            const int bkb = ks * 32 + bkq;
            uint32_t Ah[4][4], Bh[4][2], Bl[4][2];
#pragma unroll
            for (int mf = 0; mf < 4; mf++) {
                uint32_t ad = aAh + (uint32_t)((wm + mf * 16 + arow) * (ASTR * 2)) + akb;
                ldsm4(Ah[mf][0], Ah[mf][1], Ah[mf][2], Ah[mf][3], ad);
            }
#pragma unroll
            for (int nf2 = 0; nf2 < 2; nf2++) {
                uint32_t bo = (uint32_t)((wn + nf2 * 16 + brow) * (ASTR * 2)) + bkb;
                uint32_t r0, r1, r2, r3;
                ldsm4(r0, r1, r2, r3, aBh + bo);
                Bh[nf2 * 2][0] = r0; Bh[nf2 * 2][1] = r1;
                Bh[nf2 * 2 + 1][0] = r2; Bh[nf2 * 2 + 1][1] = r3;
                ldsm4(r0, r1, r2, r3, aBl + bo);
                Bl[nf2 * 2][0] = r0; Bl[nf2 * 2][1] = r1;
                Bl[nf2 * 2 + 1][0] = r2; Bl[nf2 * 2 + 1][1] = r3;
            }
#pragma unroll
            for (int mf = 0; mf < 4; mf++)
#pragma unroll
                for (int nf = 0; nf < 4; nf++) {
                    mma16816(acc[mf][nf], Ah[mf], Bh[nf]);
                    mma16816(acc[mf][nf], Ah[mf], Bl[nf]);
                }
#pragma unroll
            for (int mf = 0; mf < 4; mf++) {
                uint32_t Al[4];
                uint32_t ad = aAl + (uint32_t)((wm + mf * 16 + arow) * (ASTR * 2)) + akb;
                ldsm4(Al[0], Al[1], Al[2], Al[3], ad);
#pragma unroll
                for (int nf = 0; nf < 4; nf++)
                    mma16816(acc[mf][nf], Al, Bh[nf]);
            }
        }
    }

#pragma unroll
    for (int mf = 0; mf < 4; mf++) {
        int m = m0 + wm + mf * 16 + (lane >> 2);
        int dirA = m >> 10, gA = m & 1023;
        int mB = m + 8;
        int gB = mB & 1023;
        float biasA = dirA ? bb[gA] : bf[gA];
        float biasB = (mB >> 10) ? bb[gB] : bf[gB];
#pragma unroll
        for (int nf = 0; nf < 4; nf++) {
            int n = n0 + wn + nf * 8 + 2 * (lane & 3);
            int t = n >> 5, b = n & 31;
            float* zpA = g_zpre + ((long)dirA * TT + t) * (G4 * BB) + (long)gA * BB + b;
            *(float2*)zpA = make_float2(acc[mf][nf][0] + biasA, acc[mf][nf][1] + biasA);
            float* zpB = g_zpre + ((long)(mB >> 10) * TT + t) * (G4 * BB) + (long)gB * BB + b;
            *(float2*)zpB = make_float2(acc[mf][nf][2] + biasB, acc[mf][nf][3] + biasB);
        }
    }
}

// ============================================================================
// K1b: initialize h slots (fp32 pair-packed + bf16 split) and zero barriers
// ============================================================================
__global__ void k_inith(const float* __restrict__ h0)
{
    int dir = blockIdx.x;
    int tid = threadIdx.x;
    int slot = (dir == 0) ? 0 : TT;
    __nv_bfloat16* hbf = (__nv_bfloat16*)(g_hsbf[dir]);
    for (int s = tid; s < HHD * BB; s += 256) {
        int k = s >> 5, b = s & 31;
        float v = h0[dir * (BB * HHD) + b * HHD + k];
        g_hs[dir][slot * (HHD * BB) + (k >> 1) * 64 + b * 2 + (k & 1)] = v;
        __nv_bfloat16 hi = __float2bfloat16(v);
        float rem = v - __bfloat162float(hi);
        uint32_t wi = slot * 8192 + (k >> 1) * 64 + b * 2;
        hbf[wi * 2 + (k & 1)] = hi;
        hbf[(wi + 1) * 2 + (k & 1)] = __float2bfloat16(rem);
    }
    if (blockIdx.x == 0) {
        for (int i = tid; i < 2 * TT * BARSTR; i += 256) g_bar[i] = 0;
    }
}

// ============================================================================
// K2: persistent bi-directional LSTM recurrence, tensor-core compute.
// 128 CTAs x 384 threads: dir = bid>>6, unit group j0 = (bid&63)*4 (16 rows).
// Warps 0-7 (compute): warp w owns k in [32w, 32w+32) = kfrags {2w, 2w+1}.
//   W_hh fragments (bf16 hi/lo) preloaded in registers ONCE.
//   Per step: 16 LDG.64 of h frags (hi/lo interleaved), 24 mma.m16n8k16
//   (Wh*hh + Wl*hh + Wh*hl), STS partials to padded zred, bar.arrive 2.
// Warps 8-11 (gates): prefetch z_pre, bar.sync 2, reduce 8 partials, gates,
//   store h fp32 (for proj) + bf16 hi/lo (frag layout), per-warp release.
// ============================================================================
__global__ void __launch_bounds__(384, 1) k_lstm(const float* __restrict__ c0)
{
    __shared__ float zred[2][8][16][34];   // parity x warp x row x batch(pad 34)
    __shared__ float csm[4][32];

    const int tid = threadIdx.x;
    const int w = tid >> 5, lane = tid & 31;
    const int dir = blockIdx.x >> 6;
    const int j0 = (blockIdx.x & 63) * 4;
    const int b  = lane;

    if (w >= 8) {
        int jj = w - 8;
        csm[jj][b] = c0[dir * (BB * HHD) + b * HHD + j0 + jj];
    }
    __syncthreads();

    float* hsBase = g_hs[dir];
    uint32_t* hbfBase = g_hsbf[dir];
    int* bar = g_bar + dir * TT * BARSTR;
    const long zdirbase = (long)dir * (TT * G4 * BB);

    if (w < 8) {
        // ==================== compute warps ====================
        const int tq = lane & 3, tb = lane >> 2;
        // --- preload W_hh fragments (registers, kept whole loop) ---
        uint32_t Ah[2][4], Al[2][4];
        {
            const __nv_bfloat16* WhiB = g_Hhi + (long)dir * 1024 * 256;
            const __nv_bfloat16* WloB = g_Hlo + (long)dir * 1024 * 256;
            int rr = tb;           // frag rows rr, rr+8
            int grow1 = (rr >> 2) * 256 + j0 + (rr & 3);
            int rr8 = rr + 8;
            int grow2 = (rr8 >> 2) * 256 + j0 + (rr8 & 3);
#pragma unroll
            for (int kf = 0; kf < 2; kf++) {
                int k0 = (2 * w + kf) * 16 + tq * 2;
                Ah[kf][0] = *(const uint32_t*)(WhiB + grow1 * 256 + k0);
                Ah[kf][1] = *(const uint32_t*)(WhiB + grow2 * 256 + k0);
                Ah[kf][2] = *(const uint32_t*)(WhiB + grow1 * 256 + k0 + 8);
                Ah[kf][3] = *(const uint32_t*)(WhiB + grow2 * 256 + k0 + 8);
                Al[kf][0] = *(const uint32_t*)(WloB + grow1 * 256 + k0);
                Al[kf][1] = *(const uint32_t*)(WloB + grow2 * 256 + k0);
                Al[kf][2] = *(const uint32_t*)(WloB + grow1 * 256 + k0 + 8);
                Al[kf][3] = *(const uint32_t*)(WloB + grow2 * 256 + k0 + 8);
            }
        }
        // h frag word offsets (within a slot): q = kf*8+tq (+4), b col = tb+8nf
        const int rr = tb;
        const int q0 = w * 16 + tq;

        for (int s = 0; s < TT; s++) {
            const int t = (dir == 0) ? s : (TT - 1 - s);
            const int rslot = (dir == 0) ? s : (t + 1);
            const int par = s & 1;

            if (s > 0) {
                if (tid == 0) {
                    while (ldacq(&bar[(s - 1) * BARSTR]) < 256) pause_short();
                }
            }
            asm volatile("bar.sync 1, 256;" ::: "memory");

            // ---- load h fragments: 16 x LDG.64 (hi word + lo word) ----
            const uint32_t* hb = hbfBase + (uint32_t)rslot * 8192;
            ull Bw[2][4][2];
#pragma unroll
            for (int kf = 0; kf < 2; kf++) {
                int qa = q0 + kf * 8;
#pragma unroll
                for (int nf = 0; nf < 4; nf++) {
                    int bcol = (tb + nf * 8) * 2;
                    Bw[kf][nf][0] = *(const ull*)(hb + (qa) * 64 + bcol);
                    Bw[kf][nf][1] = *(const ull*)(hb + (qa + 4) * 64 + bcol);
                }
            }

            // ---- 24 MMAs: C[nf] += Ah*Bh + Al*Bh + Ah*Bl ----
            float C[4][4];
#pragma unroll
            for (int nf = 0; nf < 4; nf++)
#pragma unroll
                for (int q = 0; q < 4; q++) C[nf][q] = 0.f;
#pragma unroll
            for (int kf = 0; kf < 2; kf++) {
#pragma unroll
                for (int nf = 0; nf < 4; nf++) {
                    uint32_t bh[2], bl[2];
                    bh[0] = (uint32_t)(Bw[kf][nf][0]);
                    bl[0] = (uint32_t)(Bw[kf][nf][0] >> 32);
                    bh[1] = (uint32_t)(Bw[kf][nf][1]);
                    bl[1] = (uint32_t)(Bw[kf][nf][1] >> 32);
                    mma16816(C[nf], Ah[kf], bh);
                    mma16816(C[nf], Al[kf], bh);
                    mma16816(C[nf], Ah[kf], bl);
                }
            }

            // ---- write partials to zred ----
#pragma unroll
            for (int nf = 0; nf < 4; nf++) {
                int col = nf * 8 + tq * 2;
                *(float2*)&zred[par][w][rr][col]     = make_float2(C[nf][0], C[nf][1]);
                *(float2*)&zred[par][w][rr + 8][col] = make_float2(C[nf][2], C[nf][3]);
            }
            asm volatile("bar.arrive 2, 384;" ::: "memory");
        }
    } else {
        // ==================== gate warps ====================
        const int jj = w - 8;
        __nv_bfloat16* hbf16 = (__nv_bfloat16*)hbfBase;
        for (int s = 0; s < TT; s++) {
            const int t = (dir == 0) ? s : (TT - 1 - s);
            const int wslot = (dir == 0) ? (s + 1) : t;
            const int par = s & 1;

            // prefetch z_pre for this step
            const float* zb = g_zpre + zdirbase + (long)t * (G4 * BB) + (j0 + jj) * BB + b;
            float zp0 = zb[0 * HHD * BB];
            float zp1 = zb[1 * HHD * BB];
            float zp2 = zb[2 * HHD * BB];
            float zp3 = zb[3 * HHD * BB];

            asm volatile("bar.sync 2, 384;" ::: "memory");

            float zi = zp0, zf = zp1, zg = zp2, zo = zp3;
#pragma unroll
            for (int c = 0; c < 8; c++) {
                zi += zred[par][c][0 * 4 + jj][b];
                zf += zred[par][c][1 * 4 + jj][b];
                zg += zred[par][c][2 * 4 + jj][b];
                zo += zred[par][c][3 * 4 + jj][b];
            }
            float cc = sigf(zf) * csm[jj][b] + sigf(zi) * tanhfast(zg);
            csm[jj][b] = cc;
            float h = sigf(zo) * tanhfast(cc);
            int j = j0 + jj;
            // fp32 store (for k_proj)
            hsBase[wslot * (HHD * BB) + (j >> 1) * 64 + b * 2 + (j & 1)] = h;
            // bf16 hi/lo store (for recurrence fragments)
            __nv_bfloat16 hh = __float2bfloat16(h);
            float hrem = h - __bfloat162float(hh);
            uint32_t wi = (uint32_t)wslot * 8192 + (uint32_t)(j >> 1) * 64 + b * 2;
            hbf16[wi * 2 + (j & 1)] = hh;
            hbf16[(wi + 1) * 2 + (j & 1)] = __float2bfloat16(hrem);
            __syncwarp();
            if (lane == 0) redrel(&bar[s * BARSTR]);
        }
    }
}

// ============================================================================
// K3: output projection.  SMEM-staged h (64KB) + fma2. warp=tag, lane=b.
// ============================================================================
__global__ void __launch_bounds__(384) k_proj(
    const float* __restrict__ Wout, const float* __restrict__ bout)
{
    extern __shared__ float hsm[];    // [2][8192] floats = 64 KB
    const int t = blockIdx.x;
    const int tid = threadIdx.x;
    const int tag = tid >> 5;
    const int l = tid & 31;

    const float4* hf = (const float4*)(g_hs[0] + (t + 1) * (HHD * BB));
    const float4* hb = (const float4*)(g_hs[1] + t * (HHD * BB));
    float4* sf = (float4*)hsm;
    float4* sbp = (float4*)(hsm + HHD * BB);
    for (int i = tid; i < (HHD * BB) / 4; i += 384) {
        sf[i] = hf[i];
        sbp[i] = hb[i];
    }
    __syncthreads();

    const ull* w2f = (const ull*)(Wout + tag * 512);
    const ull* w2b = w2f + 128;
    const ull* hf2 = (const ull*)hsm;
    const ull* hb2 = (const ull*)(hsm + HHD * BB);

    ull a0 = 0ULL, a1 = 0ULL, a2 = 0ULL, a3 = 0ULL;
#pragma unroll
    for (int p = 0; p < 128; p += 4) {
        fma2(a0, w2f[p],     hf2[(p + 0) * 32 + l]);
        fma2(a1, w2f[p + 1], hf2[(p + 1) * 32 + l]);
        fma2(a2, w2f[p + 2], hf2[(p + 2) * 32 + l]);
        fma2(a3, w2f[p + 3], hf2[(p + 3) * 32 + l]);
    }
#pragma unroll
    for (int p = 0; p < 128; p += 4) {
        fma2(a0, w2b[p],     hb2[(p + 0) * 32 + l]);
        fma2(a1, w2b[p + 1], hb2[(p + 1) * 32 + l]);
        fma2(a2, w2b[p + 2], hb2[(p + 2) * 32 + l]);
        fma2(a3, w2b[p + 3], hb2[(p + 3) * 32 + l]);
    }
    float2 f0 = unpack2(a0), f1 = unpack2(a1);
    float2 f2 = unpack2(a2), f3 = unpack2(a3);
    float acc = ((f0.x + f0.y) + (f1.x + f1.y))
              + ((f2.x + f2.y) + (f3.x + f3.y)) + bout[tag];
    g_feats[(l * TT + t) * NT + tag] = acc;
}

// ============================================================================
// K4: Viterbi decode (one warp per batch element) + backtrace.
// ============================================================================
__global__ void __launch_bounds__(32) k_viterbi(
    const float* __restrict__ trans, float* __restrict__ out)
{
    __shared__ float tsm[NT * NT];
    __shared__ float fv[NT];
    __shared__ signed char bp[TT][NT];
    __shared__ float fsm[TT * NT];

    const int b = blockIdx.x;
    const int tid = threadIdx.x;

    const float* fb = g_feats + (long)b * TT * NT;
    for (int i = tid; i < TT * NT; i += 32) fsm[i] = fb[i];
    for (int i = tid; i < NT * NT; i += 32) tsm[i] = trans[i];
    if (tid < NT) fv[tid] = (tid == START_IDX) ? 0.0f : -10000.0f;
    __syncwarp();

    for (int t = 0; t < TT; t++) {
        float bestv = -1e30f; int bestp = 0;
        if (tid < NT) {
            bestv = fv[0] + tsm[tid * NT + 0]; bestp = 0;
#pragma unroll
            for (int p = 1; p < NT; p++) {
                float v = fv[p] + tsm[tid * NT + p];
                if (v > bestv) { bestv = v; bestp = p; }
            }
        }
        __syncwarp();
        if (tid < NT) {
            fv[tid] = bestv + fsm[t * NT + tid];
            bp[t][tid] = (signed char)bestp;
        }
        __syncwarp();
    }

    if (tid == 0) {
        float best = fv[0] + tsm[STOP_IDX * NT + 0]; int bt = 0;
#pragma unroll
        for (int n = 1; n < NT; n++) {
            float v = fv[n] + tsm[STOP_IDX * NT + n];
            if (v > best) { best = v; bt = n; }
        }
        out[b] = best;
        int tag = bt;
        for (int t = TT - 1; t >= 0; t--) {
            out[32 + b * TT + t] = (float)tag;
            tag = bp[t][tag];
        }
    }
}

// ============================================================================
extern "C" void kernel_launch(void* const* d_in, const int* in_sizes, int n_in,
                              void* d_out, int out_size)
{
    const int*   sent  = (const int*)  d_in[0];
    const float* embed = (const float*)d_in[1];
    const float* Wihf  = (const float*)d_in[2];
    const float* Whhf  = (const float*)d_in[3];
    const float* bf    = (const float*)d_in[4];
    const float* Wihb  = (const float*)d_in[5];
    const float* Whhb  = (const float*)d_in[6];
    const float* bb    = (const float*)d_in[7];
    const float* Wout  = (const float*)d_in[8];
    const float* bout  = (const float*)d_in[9];
    const float* trans = (const float*)d_in[10];
    const float* h0    = (const float*)d_in[11];
    const float* c0    = (const float*)d_in[12];
    float* out = (float*)d_out;

    cudaFuncSetAttribute(k_proj, cudaFuncAttributeMaxDynamicSharedMemorySize, 65536);

    k_convW<<<2048, 256>>>(Wihf, Wihb);
    k_convWh<<<2048, 256>>>(Whhf, Whhb);
    k_convX<<<8192, 256>>>(sent, embed);
    k_inith<<<2, 256>>>(h0);
    k_ingemm_mma<<<dim3(64, 16), 256>>>(bf, bb);
    k_lstm<<<128, 384>>>(c0);
    k_proj<<<TT, 384, 65536>>>(Wout, bout);
    k_viterbi<<<BB, 32>>>(trans, out);
}